// round 1
// baseline (speedup 1.0000x reference)
#include <cuda_runtime.h>
#include <math.h>

// Problem constants
#define Bv 4
#define Sv 2048
#define Dv 1024
#define Hv 16
#define HDv 64
#define Mv (Bv * Sv)   // 8192 rows

// Scratch (allocation-guard-safe: __device__ globals)
__device__ float g_q[(size_t)Bv * Hv * Sv * HDv];     // [B,H,S,HD]
__device__ float g_k[(size_t)Bv * Hv * Sv * HDv];
__device__ float g_v[(size_t)Bv * Hv * Sv * HDv];
__device__ float g_ctx[(size_t)Mv * Dv];              // [B*S, D]

// ---------------------------------------------------------------------------
// QKV projection: Out = X @ W^T, written directly into [B,H,S,HD] layout.
// Tile 64x64, BK=16, 256 threads, 4x4 micro-tile per thread.
// blockIdx.z selects which of Wq/Wk/Wv.
// ---------------------------------------------------------------------------
__global__ __launch_bounds__(256) void qkv_gemm_kernel(
    const float* __restrict__ X,
    const float* __restrict__ Wq,
    const float* __restrict__ Wk,
    const float* __restrict__ Wv)
{
    __shared__ float As[16][68];   // [k][m]
    __shared__ float Bs[16][68];   // [k][n]

    const float* W;
    float* Out;
    if (blockIdx.z == 0)      { W = Wq; Out = g_q; }
    else if (blockIdx.z == 1) { W = Wk; Out = g_k; }
    else                      { W = Wv; Out = g_v; }

    const int tid = threadIdx.x;
    const int tq = tid >> 4;        // 0..15 (row group)
    const int tn = tid & 15;        // 0..15 (col lane)
    const int m0 = blockIdx.y * 64;
    const int n0 = blockIdx.x * 64;

    const int lr = tid >> 2;        // 0..63  load row
    const int lc = (tid & 3) * 4;   // 0,4,8,12 load col (of BK=16)

    float acc[4][4];
#pragma unroll
    for (int i = 0; i < 4; i++)
#pragma unroll
        for (int j = 0; j < 4; j++) acc[i][j] = 0.f;

    for (int k0 = 0; k0 < Dv; k0 += 16) {
        float4 av = *(const float4*)&X[(size_t)(m0 + lr) * Dv + k0 + lc];
        float4 bv = *(const float4*)&W[(size_t)(n0 + lr) * Dv + k0 + lc];
        As[lc + 0][lr] = av.x; As[lc + 1][lr] = av.y;
        As[lc + 2][lr] = av.z; As[lc + 3][lr] = av.w;
        Bs[lc + 0][lr] = bv.x; Bs[lc + 1][lr] = bv.y;
        Bs[lc + 2][lr] = bv.z; Bs[lc + 3][lr] = bv.w;
        __syncthreads();

#pragma unroll
        for (int k = 0; k < 16; k++) {
            float4 a = *(const float4*)&As[k][tq * 4];
            float b0 = Bs[k][tn];
            float b1 = Bs[k][tn + 16];
            float b2 = Bs[k][tn + 32];
            float b3 = Bs[k][tn + 48];
            acc[0][0] += a.x * b0; acc[0][1] += a.x * b1; acc[0][2] += a.x * b2; acc[0][3] += a.x * b3;
            acc[1][0] += a.y * b0; acc[1][1] += a.y * b1; acc[1][2] += a.y * b2; acc[1][3] += a.y * b3;
            acc[2][0] += a.z * b0; acc[2][1] += a.z * b1; acc[2][2] += a.z * b2; acc[2][3] += a.z * b3;
            acc[3][0] += a.w * b0; acc[3][1] += a.w * b1; acc[3][2] += a.w * b2; acc[3][3] += a.w * b3;
        }
        __syncthreads();
    }

    // Epilogue: scatter into [B,H,S,HD]
#pragma unroll
    for (int i = 0; i < 4; i++) {
        int gm = m0 + tq * 4 + i;
        int b = gm >> 11;           // /2048
        int s = gm & (Sv - 1);
#pragma unroll
        for (int j = 0; j < 4; j++) {
            int gn = n0 + tn + 16 * j;
            int h  = gn >> 6;
            int hd = gn & 63;
            Out[((size_t)(b * Hv + h) * Sv + s) * HDv + hd] = acc[i][j];
        }
    }
}

// ---------------------------------------------------------------------------
// Flash attention (causal), fp32. BM = BN = 64, 256 threads.
// Thread (tq,tn): rows q = tq*4+i, cols n (or hd) = tn + 16*j.
// Online softmax stats held redundantly in registers of the 16-lane row group.
// ---------------------------------------------------------------------------
#define ATT_SMEM_FLOATS (4 * 64 * 68)
#define ATT_SMEM_BYTES  (ATT_SMEM_FLOATS * 4)

__global__ __launch_bounds__(256) void attn_kernel()
{
    extern __shared__ float sm[];
    float (*Qs)[68] = (float(*)[68])(sm);
    float (*Ks)[68] = (float(*)[68])(sm + 64 * 68);
    float (*Vs)[68] = (float(*)[68])(sm + 2 * 64 * 68);
    float (*Ps)[68] = (float(*)[68])(sm + 3 * 64 * 68);

    const int tid = threadIdx.x;
    const int tq = tid >> 4;
    const int tn = tid & 15;

    const int qt = blockIdx.x;      // q tile (0..31)
    const int h  = blockIdx.y;
    const int b  = blockIdx.z;
    const int q0 = qt * 64;

    const float* Qb = g_q + (size_t)(b * Hv + h) * Sv * HDv;
    const float* Kb = g_k + (size_t)(b * Hv + h) * Sv * HDv;
    const float* Vb = g_v + (size_t)(b * Hv + h) * Sv * HDv;

    // Load Q tile (64x64 floats = 1024 float4, 4 per thread)
#pragma unroll
    for (int it = 0; it < 4; it++) {
        int idx = tid + it * 256;
        int r = idx >> 4;
        int c = (idx & 15) * 4;
        float4 v = *(const float4*)&Qb[(size_t)(q0 + r) * HDv + c];
        *(float4*)&Qs[r][c] = v;
    }

    float m_reg[4], l_reg[4], o_reg[4][4];
#pragma unroll
    for (int i = 0; i < 4; i++) {
        m_reg[i] = -1e30f;
        l_reg[i] = 0.f;
#pragma unroll
        for (int j = 0; j < 4; j++) o_reg[i][j] = 0.f;
    }

    const float scl = 0.125f;   // 1/sqrt(64)
    const int ntiles = qt + 1;

    for (int kt = 0; kt < ntiles; kt++) {
        const int k0 = kt * 64;
        __syncthreads();  // previous iteration's reads of Ks/Vs/Ps done
        // Load K and V tiles
#pragma unroll
        for (int it = 0; it < 4; it++) {
            int idx = tid + it * 256;
            int r = idx >> 4;
            int c = (idx & 15) * 4;
            float4 kv = *(const float4*)&Kb[(size_t)(k0 + r) * HDv + c];
            float4 vv = *(const float4*)&Vb[(size_t)(k0 + r) * HDv + c];
            *(float4*)&Ks[r][c] = kv;
            *(float4*)&Vs[r][c] = vv;
        }
        __syncthreads();

        // S = Q K^T (4x4 per thread)
        float s[4][4];
#pragma unroll
        for (int i = 0; i < 4; i++)
#pragma unroll
            for (int j = 0; j < 4; j++) s[i][j] = 0.f;

#pragma unroll
        for (int d4 = 0; d4 < 16; d4++) {
            float4 qv[4];
#pragma unroll
            for (int i = 0; i < 4; i++)
                qv[i] = *(const float4*)&Qs[tq * 4 + i][d4 * 4];
#pragma unroll
            for (int j = 0; j < 4; j++) {
                float4 kv = *(const float4*)&Ks[tn + 16 * j][d4 * 4];
#pragma unroll
                for (int i = 0; i < 4; i++) {
                    s[i][j] += qv[i].x * kv.x + qv[i].y * kv.y
                             + qv[i].z * kv.z + qv[i].w * kv.w;
                }
            }
        }

        // scale + causal mask (mask only fires on diagonal tile by construction)
#pragma unroll
        for (int i = 0; i < 4; i++) {
            int gq = q0 + tq * 4 + i;
#pragma unroll
            for (int j = 0; j < 4; j++) {
                int gk = k0 + tn + 16 * j;
                float v = s[i][j] * scl;
                s[i][j] = (gk > gq) ? -1e30f : v;
            }
        }

        // online softmax update (16-lane row groups; xor 1,2,4,8 stays in group)
        float alpha[4];
#pragma unroll
        for (int i = 0; i < 4; i++) {
            float rm = fmaxf(fmaxf(s[i][0], s[i][1]), fmaxf(s[i][2], s[i][3]));
#pragma unroll
            for (int off = 8; off >= 1; off >>= 1)
                rm = fmaxf(rm, __shfl_xor_sync(0xffffffffu, rm, off));
            float newm = fmaxf(m_reg[i], rm);
            alpha[i] = __expf(m_reg[i] - newm);
            m_reg[i] = newm;
            float rs = 0.f;
#pragma unroll
            for (int j = 0; j < 4; j++) {
                s[i][j] = __expf(s[i][j] - newm);
                rs += s[i][j];
            }
#pragma unroll
            for (int off = 8; off >= 1; off >>= 1)
                rs += __shfl_xor_sync(0xffffffffu, rs, off);
            l_reg[i] = l_reg[i] * alpha[i] + rs;
#pragma unroll
            for (int j = 0; j < 4; j++) o_reg[i][j] *= alpha[i];
        }

        // stage P to smem
#pragma unroll
        for (int i = 0; i < 4; i++)
#pragma unroll
            for (int j = 0; j < 4; j++)
                Ps[tq * 4 + i][tn + 16 * j] = s[i][j];
        __syncthreads();

        // O += P V  (4 q-rows x 4 hd-cols per thread)
#pragma unroll
        for (int n4 = 0; n4 < 16; n4++) {
            float4 pv[4];
#pragma unroll
            for (int i = 0; i < 4; i++)
                pv[i] = *(const float4*)&Ps[tq * 4 + i][n4 * 4];
#pragma unroll
            for (int nn = 0; nn < 4; nn++) {
                float v0 = Vs[n4 * 4 + nn][tn];
                float v1 = Vs[n4 * 4 + nn][tn + 16];
                float v2 = Vs[n4 * 4 + nn][tn + 32];
                float v3 = Vs[n4 * 4 + nn][tn + 48];
#pragma unroll
                for (int i = 0; i < 4; i++) {
                    float p = ((const float*)&pv[i])[nn];
                    o_reg[i][0] += p * v0;
                    o_reg[i][1] += p * v1;
                    o_reg[i][2] += p * v2;
                    o_reg[i][3] += p * v3;
                }
            }
        }
    }

    // Epilogue: normalize and write to g_ctx [B*S, D]
#pragma unroll
    for (int i = 0; i < 4; i++) {
        float inv = 1.f / l_reg[i];
        int gq = q0 + tq * 4 + i;
        size_t base = ((size_t)b * Sv + gq) * Dv + h * HDv;
#pragma unroll
        for (int j = 0; j < 4; j++)
            g_ctx[base + tn + 16 * j] = o_reg[i][j] * inv;
    }
}

// ---------------------------------------------------------------------------
// Output projection: out = ctx @ Wo^T + bo
// ---------------------------------------------------------------------------
__global__ __launch_bounds__(256) void oproj_kernel(
    const float* __restrict__ Wo,
    const float* __restrict__ bo,
    float* __restrict__ out)
{
    __shared__ float As[16][68];
    __shared__ float Bs[16][68];

    const int tid = threadIdx.x;
    const int tq = tid >> 4;
    const int tn = tid & 15;
    const int m0 = blockIdx.y * 64;
    const int n0 = blockIdx.x * 64;
    const int lr = tid >> 2;
    const int lc = (tid & 3) * 4;

    float acc[4][4];
#pragma unroll
    for (int i = 0; i < 4; i++)
#pragma unroll
        for (int j = 0; j < 4; j++) acc[i][j] = 0.f;

    for (int k0 = 0; k0 < Dv; k0 += 16) {
        float4 av = *(const float4*)&g_ctx[(size_t)(m0 + lr) * Dv + k0 + lc];
        float4 bv = *(const float4*)&Wo[(size_t)(n0 + lr) * Dv + k0 + lc];
        As[lc + 0][lr] = av.x; As[lc + 1][lr] = av.y;
        As[lc + 2][lr] = av.z; As[lc + 3][lr] = av.w;
        Bs[lc + 0][lr] = bv.x; Bs[lc + 1][lr] = bv.y;
        Bs[lc + 2][lr] = bv.z; Bs[lc + 3][lr] = bv.w;
        __syncthreads();

#pragma unroll
        for (int k = 0; k < 16; k++) {
            float4 a = *(const float4*)&As[k][tq * 4];
            float b0 = Bs[k][tn];
            float b1 = Bs[k][tn + 16];
            float b2 = Bs[k][tn + 32];
            float b3 = Bs[k][tn + 48];
            acc[0][0] += a.x * b0; acc[0][1] += a.x * b1; acc[0][2] += a.x * b2; acc[0][3] += a.x * b3;
            acc[1][0] += a.y * b0; acc[1][1] += a.y * b1; acc[1][2] += a.y * b2; acc[1][3] += a.y * b3;
            acc[2][0] += a.z * b0; acc[2][1] += a.z * b1; acc[2][2] += a.z * b2; acc[2][3] += a.z * b3;
            acc[3][0] += a.w * b0; acc[3][1] += a.w * b1; acc[3][2] += a.w * b2; acc[3][3] += a.w * b3;
        }
        __syncthreads();
    }

#pragma unroll
    for (int i = 0; i < 4; i++) {
        int gm = m0 + tq * 4 + i;
#pragma unroll
        for (int j = 0; j < 4; j++) {
            int gn = n0 + tn + 16 * j;
            out[(size_t)gm * Dv + gn] = acc[i][j] + bo[gn];
        }
    }
}

// ---------------------------------------------------------------------------
extern "C" void kernel_launch(void* const* d_in, const int* in_sizes, int n_in,
                              void* d_out, int out_size)
{
    const float* X  = (const float*)d_in[0];
    const float* Wq = (const float*)d_in[1];
    const float* Wk = (const float*)d_in[2];
    const float* Wv = (const float*)d_in[3];
    const float* Wo = (const float*)d_in[4];
    const float* bo = (const float*)d_in[5];
    float* out = (float*)d_out;

    // Q/K/V projections (z selects the weight)
    qkv_gemm_kernel<<<dim3(Dv / 64, Mv / 64, 3), 256>>>(X, Wq, Wk, Wv);

    // Causal flash attention
    cudaFuncSetAttribute(attn_kernel,
                         cudaFuncAttributeMaxDynamicSharedMemorySize,
                         ATT_SMEM_BYTES);
    attn_kernel<<<dim3(Sv / 64, Hv, Bv), 256, ATT_SMEM_BYTES>>>();

    // Output projection + bias
    oproj_kernel<<<dim3(Dv / 64, Mv / 64), 256>>>(Wo, bo, out);
}

// round 3
// speedup vs baseline: 4.7397x; 4.7397x over previous
#include <cuda_runtime.h>
#include <cuda_bf16.h>
#include <math.h>
#include <stdint.h>

// Problem constants
#define Bv 4
#define Sv 2048
#define Dv 1024
#define Hv 16
#define HDv 64
#define Mv (Bv * Sv)   // 8192 rows

// ---------------------------------------------------------------------------
// PTX helpers (sm_80+ baseline: mma.sync / ldmatrix / cp.async)
// ---------------------------------------------------------------------------
__device__ __forceinline__ uint32_t smem_to_u32(const void* p) {
    uint32_t a;
    asm("{ .reg .u64 t; cvta.to.shared.u64 t, %1; cvt.u32.u64 %0, t; }"
        : "=r"(a) : "l"(p));
    return a;
}

__device__ __forceinline__ void mma_bf16(float* c, const uint32_t* a,
                                         uint32_t b0, uint32_t b1) {
    asm volatile(
        "mma.sync.aligned.m16n8k16.row.col.f32.bf16.bf16.f32 "
        "{%0,%1,%2,%3}, {%4,%5,%6,%7}, {%8,%9}, {%0,%1,%2,%3};\n"
        : "+f"(c[0]), "+f"(c[1]), "+f"(c[2]), "+f"(c[3])
        : "r"(a[0]), "r"(a[1]), "r"(a[2]), "r"(a[3]), "r"(b0), "r"(b1));
}

__device__ __forceinline__ void ldm_x4(uint32_t* r, uint32_t a) {
    asm volatile("ldmatrix.sync.aligned.m8n8.x4.shared.b16 {%0,%1,%2,%3}, [%4];"
        : "=r"(r[0]), "=r"(r[1]), "=r"(r[2]), "=r"(r[3]) : "r"(a));
}
__device__ __forceinline__ void ldm_x4_t(uint32_t* r, uint32_t a) {
    asm volatile("ldmatrix.sync.aligned.m8n8.x4.trans.shared.b16 {%0,%1,%2,%3}, [%4];"
        : "=r"(r[0]), "=r"(r[1]), "=r"(r[2]), "=r"(r[3]) : "r"(a));
}

__device__ __forceinline__ void cp16(uint32_t dst, const void* src) {
    asm volatile("cp.async.cg.shared.global [%0], [%1], 16;"
        :: "r"(dst), "l"(src) : "memory");
}
#define CP_COMMIT() asm volatile("cp.async.commit_group;" ::: "memory")
#define CP_WAIT(N)  asm volatile("cp.async.wait_group %0;" :: "n"(N) : "memory")

// row-of-128B XOR swizzle (conflict-free ldmatrix)
__device__ __forceinline__ uint32_t swaddr(uint32_t base, int row, int unit) {
    uint32_t off = (uint32_t)row * 128u + (uint32_t)unit * 16u;
    return base + (off ^ ((off >> 3) & 0x70u));
}

// split float pair -> packed bf16x2 hi (returned) and lo (out param)
__device__ __forceinline__ uint32_t split2(float x, float y, uint32_t& lo) {
    __nv_bfloat16 hx = __float2bfloat16(x);
    __nv_bfloat16 hy = __float2bfloat16(y);
    __nv_bfloat162 hp(hx, hy);
    __nv_bfloat162 lp(__float2bfloat16(x - __bfloat162float(hx)),
                      __float2bfloat16(y - __bfloat162float(hy)));
    lo = *(uint32_t*)&lp;
    return *(uint32_t*)&hp;
}

// ---------------------------------------------------------------------------
// Scratch (allocation-guard-safe: __device__ globals), all bf16 hi/lo pairs
// ---------------------------------------------------------------------------
#define QKV_ELEMS ((size_t)Bv * Hv * Sv * HDv)
__device__ __nv_bfloat16 g_qhi[QKV_ELEMS], g_qlo[QKV_ELEMS];
__device__ __nv_bfloat16 g_khi[QKV_ELEMS], g_klo[QKV_ELEMS];
__device__ __nv_bfloat16 g_vhi[QKV_ELEMS], g_vlo[QKV_ELEMS];
__device__ __nv_bfloat16 g_xhi[(size_t)Mv * Dv], g_xlo[(size_t)Mv * Dv];
__device__ __nv_bfloat16 g_whi[(size_t)4 * Dv * Dv], g_wlo[(size_t)4 * Dv * Dv];
__device__ __nv_bfloat16 g_chi[(size_t)Mv * Dv], g_clo[(size_t)Mv * Dv];

// ---------------------------------------------------------------------------
// fp32 -> bf16 hi/lo split. which: 0=X, 1..4=W[which-1]
// ---------------------------------------------------------------------------
__global__ __launch_bounds__(256) void cvt_split_kernel(
    const float4* __restrict__ src, int which, int n4)
{
    int i = blockIdx.x * blockDim.x + threadIdx.x;
    if (i >= n4) return;
    __nv_bfloat16 *hi, *lo;
    if (which == 0) { hi = g_xhi; lo = g_xlo; }
    else            { hi = g_whi + (size_t)(which - 1) * Dv * Dv;
                      lo = g_wlo + (size_t)(which - 1) * Dv * Dv; }
    float4 v = src[i];
    uint32_t l0, l1;
    uint32_t h0 = split2(v.x, v.y, l0);
    uint32_t h1 = split2(v.z, v.w, l1);
    uint32_t* hp = (uint32_t*)(hi + (size_t)i * 4);
    uint32_t* lp = (uint32_t*)(lo + (size_t)i * 4);
    hp[0] = h0; hp[1] = h1;
    lp[0] = l0; lp[1] = l1;
}

// ---------------------------------------------------------------------------
// Tensor-core GEMM: Out[M,N] = A[M,K] @ B[N,K]^T, bf16 hi/lo 3-pass, fp32 acc.
// Block 128x128, BK=64, 8 warps (2x4 -> warp tile 64x32), 2-stage cp.async.
// mode 0: A = X split, B = W[z], epilogue -> g_{q,k,v}{hi,lo} in [B,H,S,HD]
// mode 1: A = ctx split, B = W[3], epilogue -> fp32 out + bias
// ---------------------------------------------------------------------------
#define TB 16384                       // one 128x64-bf16 tile (128 rows x 128B)
#define GEMM_SMEM (2 * 4 * TB)         // 2 stages x (Ahi,Alo,Bhi,Blo)

__global__ __launch_bounds__(256) void gemm_tc(
    int mode, float* __restrict__ out, const float* __restrict__ bias)
{
    extern __shared__ char smem[];
    uint32_t sb = smem_to_u32(smem);
    const int tid = threadIdx.x;
    const int wid = tid >> 5, lane = tid & 31;
    const int wm = wid & 1, wn = wid >> 1;
    const int m0 = blockIdx.y * 128, n0 = blockIdx.x * 128;

    const __nv_bfloat16 *Ahi, *Alo, *Bhi, *Blo;
    if (mode == 0) {
        int w = blockIdx.z;
        Ahi = g_xhi; Alo = g_xlo;
        Bhi = g_whi + (size_t)w * Dv * Dv;
        Blo = g_wlo + (size_t)w * Dv * Dv;
    } else {
        Ahi = g_chi; Alo = g_clo;
        Bhi = g_whi + (size_t)3 * Dv * Dv;
        Blo = g_wlo + (size_t)3 * Dv * Dv;
    }

    auto issue = [&](int ch, int stg) {
        uint32_t base = sb + (uint32_t)stg * (4 * TB);
        int k0 = ch * 64;
#pragma unroll
        for (int it = 0; it < 4; it++) {
            int idx = tid + it * 256;
            int row = idx >> 3, u = idx & 7;
            uint32_t off = (uint32_t)row * 128u + (uint32_t)u * 16u;
            uint32_t swo = off ^ ((off >> 3) & 0x70u);
            size_t ga = (size_t)(m0 + row) * Dv + k0 + u * 8;
            size_t gb = (size_t)(n0 + row) * Dv + k0 + u * 8;
            cp16(base + swo,          Ahi + ga);
            cp16(base + TB + swo,     Alo + ga);
            cp16(base + 2 * TB + swo, Bhi + gb);
            cp16(base + 3 * TB + swo, Blo + gb);
        }
        CP_COMMIT();
    };

    float acc[4][4][4];
#pragma unroll
    for (int i = 0; i < 4; i++)
#pragma unroll
        for (int j = 0; j < 4; j++)
#pragma unroll
            for (int k = 0; k < 4; k++) acc[i][j][k] = 0.f;

    issue(0, 0);

    const int lrow = lane & 15, lsel = lane >> 4;

    for (int ch = 0; ch < 16; ch++) {
        if (ch + 1 < 16) { issue(ch + 1, (ch + 1) & 1); CP_WAIT(1); }
        else             { CP_WAIT(0); }
        __syncthreads();

        uint32_t base = sb + (uint32_t)(ch & 1) * (4 * TB);
#pragma unroll
        for (int ks = 0; ks < 4; ks++) {
            uint32_t ah[4][4], al[4][4], bh[2][4], bl[2][4];
#pragma unroll
            for (int mi = 0; mi < 4; mi++) {
                ldm_x4(ah[mi], swaddr(base,      wm * 64 + 16 * mi + lrow, 2 * ks + lsel));
                ldm_x4(al[mi], swaddr(base + TB, wm * 64 + 16 * mi + lrow, 2 * ks + lsel));
            }
#pragma unroll
            for (int p = 0; p < 2; p++) {
                ldm_x4(bh[p], swaddr(base + 2 * TB, wn * 32 + 16 * p + lrow, 2 * ks + lsel));
                ldm_x4(bl[p], swaddr(base + 3 * TB, wn * 32 + 16 * p + lrow, 2 * ks + lsel));
            }
#pragma unroll
            for (int mi = 0; mi < 4; mi++)
#pragma unroll
                for (int nt = 0; nt < 4; nt++) {
                    int p = nt >> 1, q = nt & 1;
                    mma_bf16(acc[mi][nt], ah[mi], bh[p][q], bh[p][q + 2]);
                    mma_bf16(acc[mi][nt], ah[mi], bl[p][q], bl[p][q + 2]);
                    mma_bf16(acc[mi][nt], al[mi], bh[p][q], bh[p][q + 2]);
                }
        }
        __syncthreads();
    }

    // Epilogue
    const int g = lane >> 2, t4 = lane & 3;
    __nv_bfloat16 *dhi = nullptr, *dlo = nullptr;
    if (mode == 0) {
        int w = blockIdx.z;
        dhi = (w == 0) ? g_qhi : (w == 1) ? g_khi : g_vhi;
        dlo = (w == 0) ? g_qlo : (w == 1) ? g_klo : g_vlo;
    }
#pragma unroll
    for (int mi = 0; mi < 4; mi++)
#pragma unroll
        for (int nt = 0; nt < 4; nt++)
#pragma unroll
            for (int hf = 0; hf < 2; hf++) {
                int row = m0 + wm * 64 + 16 * mi + g + 8 * hf;
                int col = n0 + wn * 32 + 8 * nt + 2 * t4;
                float v0 = acc[mi][nt][2 * hf];
                float v1 = acc[mi][nt][2 * hf + 1];
                if (mode == 0) {
                    int bb = row >> 11, s = row & (Sv - 1);
                    int hh = col >> 6, hd = col & 63;
                    size_t di = ((size_t)(bb * Hv + hh) * Sv + s) * HDv + hd;
                    uint32_t lo2;
                    uint32_t hi2 = split2(v0, v1, lo2);
                    *(uint32_t*)(dhi + di) = hi2;
                    *(uint32_t*)(dlo + di) = lo2;
                } else {
                    out[(size_t)row * Dv + col]     = v0 + bias[col];
                    out[(size_t)row * Dv + col + 1] = v1 + bias[col + 1];
                }
            }
}

// ---------------------------------------------------------------------------
// Tensor-core causal flash attention. BM=BN=64, 4 warps (warp = 16 q rows).
// QK^T and PV both 3-pass bf16 hi/lo. Writes ctx as bf16 hi/lo [B*S, D].
// ---------------------------------------------------------------------------
#define ATB 8192                 // one 64x64-bf16 tile
#define ATT_SMEM (6 * ATB)       // Qhi Qlo Khi Klo Vhi Vlo

__global__ __launch_bounds__(128) void attn_tc()
{
    extern __shared__ char sm_[];
    uint32_t sb = smem_to_u32(sm_);
    const int tid = threadIdx.x, wid = tid >> 5, lane = tid & 31;
    const int qt = blockIdx.x, h = blockIdx.y, b = blockIdx.z;
    const int q0 = qt * 64;
    const size_t hb = (size_t)(b * Hv + h) * Sv * HDv;
    const __nv_bfloat16 *Qhi = g_qhi + hb, *Qlo = g_qlo + hb;
    const __nv_bfloat16 *Khi = g_khi + hb, *Klo = g_klo + hb;
    const __nv_bfloat16 *Vhi = g_vhi + hb, *Vlo = g_vlo + hb;

    // Load Q tiles (64 rows x 8 16B-units), swizzled
#pragma unroll
    for (int it = 0; it < 4; it++) {
        int idx = tid + it * 128;
        int row = idx >> 3, u = idx & 7;
        uint32_t off = (uint32_t)row * 128u + (uint32_t)u * 16u;
        off ^= (off >> 3) & 0x70u;
        size_t gs = (size_t)(q0 + row) * HDv + u * 8;
        *(uint4*)(sm_ + off)       = *(const uint4*)(Qhi + gs);
        *(uint4*)(sm_ + ATB + off) = *(const uint4*)(Qlo + gs);
    }

    const int lrow = lane & 15, lsel = lane >> 4, g = lane >> 2, t4 = lane & 3;
    const float scl = 0.125f;

    float mreg[2] = {-1e30f, -1e30f}, lreg[2] = {0.f, 0.f};
    float o[8][4];
#pragma unroll
    for (int nt = 0; nt < 8; nt++)
#pragma unroll
        for (int k = 0; k < 4; k++) o[nt][k] = 0.f;

    const int gq0 = q0 + wid * 16 + g;
    const int gq1 = gq0 + 8;

    for (int kt = 0; kt <= qt; kt++) {
        __syncthreads();
        const int k0r = kt * 64;
#pragma unroll
        for (int it = 0; it < 4; it++) {
            int idx = tid + it * 128;
            int row = idx >> 3, u = idx & 7;
            uint32_t off = (uint32_t)row * 128u + (uint32_t)u * 16u;
            off ^= (off >> 3) & 0x70u;
            size_t gs = (size_t)(k0r + row) * HDv + u * 8;
            *(uint4*)(sm_ + 2 * ATB + off) = *(const uint4*)(Khi + gs);
            *(uint4*)(sm_ + 3 * ATB + off) = *(const uint4*)(Klo + gs);
            *(uint4*)(sm_ + 4 * ATB + off) = *(const uint4*)(Vhi + gs);
            *(uint4*)(sm_ + 5 * ATB + off) = *(const uint4*)(Vlo + gs);
        }
        __syncthreads();

        // ---- S = Q K^T (3-pass hi/lo) ----
        float s[8][4];
#pragma unroll
        for (int nt = 0; nt < 8; nt++)
#pragma unroll
            for (int k = 0; k < 4; k++) s[nt][k] = 0.f;

#pragma unroll
        for (int ks = 0; ks < 4; ks++) {
            uint32_t qh[4], ql[4];
            ldm_x4(qh, swaddr(sb,       wid * 16 + lrow, 2 * ks + lsel));
            ldm_x4(ql, swaddr(sb + ATB, wid * 16 + lrow, 2 * ks + lsel));
            uint32_t kh[4][4], kl[4][4];
#pragma unroll
            for (int p = 0; p < 4; p++) {
                ldm_x4(kh[p], swaddr(sb + 2 * ATB, 16 * p + lrow, 2 * ks + lsel));
                ldm_x4(kl[p], swaddr(sb + 3 * ATB, 16 * p + lrow, 2 * ks + lsel));
            }
#pragma unroll
            for (int nt = 0; nt < 8; nt++) {
                int p = nt >> 1, q = nt & 1;
                mma_bf16(s[nt], qh, kh[p][q], kh[p][q + 2]);
                mma_bf16(s[nt], qh, kl[p][q], kl[p][q + 2]);
                mma_bf16(s[nt], ql, kh[p][q], kh[p][q + 2]);
            }
        }

        // scale + causal mask (only diagonal tile can mask)
        const bool diag = (kt == qt);
#pragma unroll
        for (int nt = 0; nt < 8; nt++) {
            int c0 = k0r + 8 * nt + 2 * t4;
            s[nt][0] *= scl; s[nt][1] *= scl; s[nt][2] *= scl; s[nt][3] *= scl;
            if (diag) {
                if (c0 > gq0)     s[nt][0] = -1e30f;
                if (c0 + 1 > gq0) s[nt][1] = -1e30f;
                if (c0 > gq1)     s[nt][2] = -1e30f;
                if (c0 + 1 > gq1) s[nt][3] = -1e30f;
            }
        }

        // ---- online softmax (rows owned by lane quads) ----
        float rm0 = -1e30f, rm1 = -1e30f;
#pragma unroll
        for (int nt = 0; nt < 8; nt++) {
            rm0 = fmaxf(rm0, fmaxf(s[nt][0], s[nt][1]));
            rm1 = fmaxf(rm1, fmaxf(s[nt][2], s[nt][3]));
        }
        rm0 = fmaxf(rm0, __shfl_xor_sync(0xffffffffu, rm0, 1));
        rm0 = fmaxf(rm0, __shfl_xor_sync(0xffffffffu, rm0, 2));
        rm1 = fmaxf(rm1, __shfl_xor_sync(0xffffffffu, rm1, 1));
        rm1 = fmaxf(rm1, __shfl_xor_sync(0xffffffffu, rm1, 2));

        float nm0 = fmaxf(mreg[0], rm0), nm1 = fmaxf(mreg[1], rm1);
        float a0 = __expf(mreg[0] - nm0), a1 = __expf(mreg[1] - nm1);
        mreg[0] = nm0; mreg[1] = nm1;

        float rs0 = 0.f, rs1 = 0.f;
#pragma unroll
        for (int nt = 0; nt < 8; nt++) {
            s[nt][0] = __expf(s[nt][0] - nm0);
            s[nt][1] = __expf(s[nt][1] - nm0);
            s[nt][2] = __expf(s[nt][2] - nm1);
            s[nt][3] = __expf(s[nt][3] - nm1);
            rs0 += s[nt][0] + s[nt][1];
            rs1 += s[nt][2] + s[nt][3];
        }
        rs0 += __shfl_xor_sync(0xffffffffu, rs0, 1);
        rs0 += __shfl_xor_sync(0xffffffffu, rs0, 2);
        rs1 += __shfl_xor_sync(0xffffffffu, rs1, 1);
        rs1 += __shfl_xor_sync(0xffffffffu, rs1, 2);
        lreg[0] = lreg[0] * a0 + rs0;
        lreg[1] = lreg[1] * a1 + rs1;

#pragma unroll
        for (int nt = 0; nt < 8; nt++) {
            o[nt][0] *= a0; o[nt][1] *= a0;
            o[nt][2] *= a1; o[nt][3] *= a1;
        }

        // ---- O += P V (3-pass: Phi*Vhi + Plo*Vhi + Phi*Vlo) ----
#pragma unroll
        for (int ks = 0; ks < 4; ks++) {
            // P fragments from S accumulator layout identity
            uint32_t ph[4], pl[4];
            ph[0] = split2(s[2 * ks][0],     s[2 * ks][1],     pl[0]);
            ph[1] = split2(s[2 * ks][2],     s[2 * ks][3],     pl[1]);
            ph[2] = split2(s[2 * ks + 1][0], s[2 * ks + 1][1], pl[2]);
            ph[3] = split2(s[2 * ks + 1][2], s[2 * ks + 1][3], pl[3]);

            uint32_t vh[4][4], vl[4][4];
#pragma unroll
            for (int p2 = 0; p2 < 4; p2++) {
                ldm_x4_t(vh[p2], swaddr(sb + 4 * ATB, 16 * ks + lrow, 2 * p2 + lsel));
                ldm_x4_t(vl[p2], swaddr(sb + 5 * ATB, 16 * ks + lrow, 2 * p2 + lsel));
            }
#pragma unroll
            for (int nt = 0; nt < 8; nt++) {
                int p2 = nt >> 1, q = nt & 1;
                uint32_t b0h = vh[p2][2 * q], b1h = vh[p2][2 * q + 1];
                uint32_t b0l = vl[p2][2 * q], b1l = vl[p2][2 * q + 1];
                mma_bf16(o[nt], ph, b0h, b1h);
                mma_bf16(o[nt], pl, b0h, b1h);
                mma_bf16(o[nt], ph, b0l, b1l);
            }
        }
    }

    // Epilogue: normalize, split hi/lo, write ctx [B*S, D]
    float inv0 = 1.f / lreg[0], inv1 = 1.f / lreg[1];
#pragma unroll
    for (int nt = 0; nt < 8; nt++) {
        int col = h * HDv + 8 * nt + 2 * t4;
        size_t r0 = ((size_t)b * Sv + gq0) * Dv + col;
        size_t r1 = ((size_t)b * Sv + gq1) * Dv + col;
        uint32_t lo2;
        uint32_t hi2 = split2(o[nt][0] * inv0, o[nt][1] * inv0, lo2);
        *(uint32_t*)(g_chi + r0) = hi2;
        *(uint32_t*)(g_clo + r0) = lo2;
        hi2 = split2(o[nt][2] * inv1, o[nt][3] * inv1, lo2);
        *(uint32_t*)(g_chi + r1) = hi2;
        *(uint32_t*)(g_clo + r1) = lo2;
    }
}

// ---------------------------------------------------------------------------
extern "C" void kernel_launch(void* const* d_in, const int* in_sizes, int n_in,
                              void* d_out, int out_size)
{
    const float* X  = (const float*)d_in[0];
    const float* Wq = (const float*)d_in[1];
    const float* Wk = (const float*)d_in[2];
    const float* Wv = (const float*)d_in[3];
    const float* Wo = (const float*)d_in[4];
    const float* bo = (const float*)d_in[5];
    float* out = (float*)d_out;

    cudaFuncSetAttribute(gemm_tc,
                         cudaFuncAttributeMaxDynamicSharedMemorySize, GEMM_SMEM);
    cudaFuncSetAttribute(attn_tc,
                         cudaFuncAttributeMaxDynamicSharedMemorySize, ATT_SMEM);

    const int nX4 = Mv * Dv / 4;
    const int nW4 = Dv * Dv / 4;

    // 1. bf16 hi/lo splits
    cvt_split_kernel<<<(nX4 + 255) / 256, 256>>>((const float4*)X,  0, nX4);
    cvt_split_kernel<<<(nW4 + 255) / 256, 256>>>((const float4*)Wq, 1, nW4);
    cvt_split_kernel<<<(nW4 + 255) / 256, 256>>>((const float4*)Wk, 2, nW4);
    cvt_split_kernel<<<(nW4 + 255) / 256, 256>>>((const float4*)Wv, 3, nW4);
    cvt_split_kernel<<<(nW4 + 255) / 256, 256>>>((const float4*)Wo, 4, nW4);

    // 2. Q/K/V projections (tensor cores)
    gemm_tc<<<dim3(Dv / 128, Mv / 128, 3), 256, GEMM_SMEM>>>(0, nullptr, nullptr);

    // 3. Causal flash attention (tensor cores)
    attn_tc<<<dim3(Sv / 64, Hv, Bv), 128, ATT_SMEM>>>();

    // 4. Output projection + bias (tensor cores)
    gemm_tc<<<dim3(Dv / 128, Mv / 128, 1), 256, GEMM_SMEM>>>(1, out, bo);
}

// round 5
// speedup vs baseline: 4.8524x; 1.0238x over previous
#include <cuda_runtime.h>
#include <cuda_bf16.h>
#include <math.h>
#include <stdint.h>

// Problem constants
#define Bv 4
#define Sv 2048
#define Dv 1024
#define Hv 16
#define HDv 64
#define Mv (Bv * Sv)   // 8192 rows

// ---------------------------------------------------------------------------
// PTX helpers (sm_80+ baseline: mma.sync / ldmatrix / cp.async)
// ---------------------------------------------------------------------------
__device__ __forceinline__ uint32_t smem_to_u32(const void* p) {
    uint32_t a;
    asm("{ .reg .u64 t; cvta.to.shared.u64 t, %1; cvt.u32.u64 %0, t; }"
        : "=r"(a) : "l"(p));
    return a;
}

__device__ __forceinline__ void mma_bf16(float* c, const uint32_t* a,
                                         uint32_t b0, uint32_t b1) {
    asm volatile(
        "mma.sync.aligned.m16n8k16.row.col.f32.bf16.bf16.f32 "
        "{%0,%1,%2,%3}, {%4,%5,%6,%7}, {%8,%9}, {%0,%1,%2,%3};\n"
        : "+f"(c[0]), "+f"(c[1]), "+f"(c[2]), "+f"(c[3])
        : "r"(a[0]), "r"(a[1]), "r"(a[2]), "r"(a[3]), "r"(b0), "r"(b1));
}

__device__ __forceinline__ void ldm_x4(uint32_t* r, uint32_t a) {
    asm volatile("ldmatrix.sync.aligned.m8n8.x4.shared.b16 {%0,%1,%2,%3}, [%4];"
        : "=r"(r[0]), "=r"(r[1]), "=r"(r[2]), "=r"(r[3]) : "r"(a));
}
__device__ __forceinline__ void ldm_x4_t(uint32_t* r, uint32_t a) {
    asm volatile("ldmatrix.sync.aligned.m8n8.x4.trans.shared.b16 {%0,%1,%2,%3}, [%4];"
        : "=r"(r[0]), "=r"(r[1]), "=r"(r[2]), "=r"(r[3]) : "r"(a));
}

__device__ __forceinline__ void cp16(uint32_t dst, const void* src) {
    asm volatile("cp.async.cg.shared.global [%0], [%1], 16;"
        :: "r"(dst), "l"(src) : "memory");
}
#define CP_COMMIT() asm volatile("cp.async.commit_group;" ::: "memory")
#define CP_WAIT(N)  asm volatile("cp.async.wait_group %0;" :: "n"(N) : "memory")

// 128B-row XOR swizzle (conflict-free ldmatrix), for 64-col bf16 tiles
__device__ __forceinline__ uint32_t swaddr(uint32_t base, int row, int unit) {
    uint32_t off = (uint32_t)row * 128u + (uint32_t)unit * 16u;
    return base + (off ^ ((off >> 3) & 0x70u));
}
// 64B-row XOR swizzle, for 32-col bf16 tiles (BK=32 GEMM stages)
__device__ __forceinline__ uint32_t swaddr64(uint32_t base, int row, int unit) {
    uint32_t off = (uint32_t)row * 64u + (uint32_t)unit * 16u;
    return base + (off ^ ((off >> 3) & 0x30u));
}

// split float pair -> packed bf16x2 hi (returned) and lo (out param)
__device__ __forceinline__ uint32_t split2(float x, float y, uint32_t& lo) {
    __nv_bfloat16 hx = __float2bfloat16(x);
    __nv_bfloat16 hy = __float2bfloat16(y);
    __nv_bfloat162 hp(hx, hy);
    __nv_bfloat162 lp(__float2bfloat16(x - __bfloat162float(hx)),
                      __float2bfloat16(y - __bfloat162float(hy)));
    lo = *(uint32_t*)&lp;
    return *(uint32_t*)&hp;
}

// ---------------------------------------------------------------------------
// Scratch (allocation-guard-safe: __device__ globals), all bf16 hi/lo pairs
// ---------------------------------------------------------------------------
#define QKV_ELEMS ((size_t)Bv * Hv * Sv * HDv)
__device__ __nv_bfloat16 g_qhi[QKV_ELEMS], g_qlo[QKV_ELEMS];
__device__ __nv_bfloat16 g_khi[QKV_ELEMS], g_klo[QKV_ELEMS];
__device__ __nv_bfloat16 g_vhi[QKV_ELEMS], g_vlo[QKV_ELEMS];
__device__ __nv_bfloat16 g_xhi[(size_t)Mv * Dv], g_xlo[(size_t)Mv * Dv];
__device__ __nv_bfloat16 g_whi[(size_t)4 * Dv * Dv], g_wlo[(size_t)4 * Dv * Dv];
__device__ __nv_bfloat16 g_chi[(size_t)Mv * Dv], g_clo[(size_t)Mv * Dv];

// ---------------------------------------------------------------------------
// fp32 -> bf16 hi/lo splits
// ---------------------------------------------------------------------------
__global__ __launch_bounds__(256) void cvt_x_kernel(const float4* __restrict__ src)
{
    int i = blockIdx.x * blockDim.x + threadIdx.x;   // < Mv*Dv/4
    float4 v = src[i];
    uint32_t l0, l1;
    uint32_t h0 = split2(v.x, v.y, l0);
    uint32_t h1 = split2(v.z, v.w, l1);
    uint32_t* hp = (uint32_t*)(g_xhi + (size_t)i * 4);
    uint32_t* lp = (uint32_t*)(g_xlo + (size_t)i * 4);
    hp[0] = h0; hp[1] = h1;
    lp[0] = l0; lp[1] = l1;
}

__global__ __launch_bounds__(256) void cvt_w_kernel(
    const float4* __restrict__ w0, const float4* __restrict__ w1,
    const float4* __restrict__ w2, const float4* __restrict__ w3)
{
    int i = blockIdx.x * blockDim.x + threadIdx.x;   // < Dv*Dv/4
    int w = blockIdx.y;
    const float4* src = (w == 0) ? w0 : (w == 1) ? w1 : (w == 2) ? w2 : w3;
    __nv_bfloat16* hi = g_whi + (size_t)w * Dv * Dv;
    __nv_bfloat16* lo = g_wlo + (size_t)w * Dv * Dv;
    float4 v = src[i];
    uint32_t l0, l1;
    uint32_t h0 = split2(v.x, v.y, l0);
    uint32_t h1 = split2(v.z, v.w, l1);
    uint32_t* hp = (uint32_t*)(hi + (size_t)i * 4);
    uint32_t* lp = (uint32_t*)(lo + (size_t)i * 4);
    hp[0] = h0; hp[1] = h1;
    lp[0] = l0; lp[1] = l1;
}

// ---------------------------------------------------------------------------
// Tensor-core GEMM: Out[M,N] = A[M,K] @ B[N,K]^T, bf16 hi/lo 3-pass, fp32 acc.
// Block 128x128, BK=32, 8 warps (warp tile 64x32), 3-stage cp.async pipeline.
// mode 0: A = X split, B = W[z], epilogue -> g_{q,k,v}{hi,lo} in [B,H,S,HD]
// mode 1: A = ctx split, B = W[3], epilogue -> fp32 out + bias
// ---------------------------------------------------------------------------
#define STG 32768                      // one stage: Ahi,Alo,Bhi,Blo x 8KB
#define GEMM_SMEM (3 * STG)            // 96 KB -> 2 CTAs/SM
#define NCH 32                         // K / 32

__global__ __launch_bounds__(256, 2) void gemm_tc(
    int mode, float* __restrict__ out, const float* __restrict__ bias)
{
    extern __shared__ char smem[];
    uint32_t sb = smem_to_u32(smem);
    const int tid = threadIdx.x;
    const int wid = tid >> 5, lane = tid & 31;
    const int wm = wid & 1, wn = wid >> 1;
    const int m0 = blockIdx.y * 128, n0 = blockIdx.x * 128;

    const __nv_bfloat16 *Ahi, *Alo, *Bhi, *Blo;
    if (mode == 0) {
        int w = blockIdx.z;
        Ahi = g_xhi; Alo = g_xlo;
        Bhi = g_whi + (size_t)w * Dv * Dv;
        Blo = g_wlo + (size_t)w * Dv * Dv;
    } else {
        Ahi = g_chi; Alo = g_clo;
        Bhi = g_whi + (size_t)3 * Dv * Dv;
        Blo = g_wlo + (size_t)3 * Dv * Dv;
    }

    auto issue = [&](int ch, int stg) {
        uint32_t base = sb + (uint32_t)stg * STG;
        int k0 = ch * 32;
#pragma unroll
        for (int it = 0; it < 2; it++) {
            int idx = tid + it * 256;        // 0..511
            int row = idx >> 2, u = idx & 3;
            size_t ga = (size_t)(m0 + row) * Dv + k0 + u * 8;
            size_t gb = (size_t)(n0 + row) * Dv + k0 + u * 8;
            cp16(swaddr64(base,         row, u), Ahi + ga);
            cp16(swaddr64(base + 8192,  row, u), Alo + ga);
            cp16(swaddr64(base + 16384, row, u), Bhi + gb);
            cp16(swaddr64(base + 24576, row, u), Blo + gb);
        }
        CP_COMMIT();
    };

    float acc[4][4][4];
#pragma unroll
    for (int i = 0; i < 4; i++)
#pragma unroll
        for (int j = 0; j < 4; j++)
#pragma unroll
            for (int k = 0; k < 4; k++) acc[i][j][k] = 0.f;

    issue(0, 0);
    issue(1, 1);

    const int lrow = lane & 15, lsel = lane >> 4;

    for (int ch = 0; ch < NCH; ch++) {
        if (ch < NCH - 1) { CP_WAIT(1); } else { CP_WAIT(0); }
        __syncthreads();
        if (ch + 2 < NCH) issue(ch + 2, (ch + 2) % 3);

        uint32_t base = sb + (uint32_t)(ch % 3) * STG;
#pragma unroll
        for (int ks = 0; ks < 2; ks++) {
            uint32_t ah[4][4], al[4][4], bh[2][4], bl[2][4];
#pragma unroll
            for (int mi = 0; mi < 4; mi++) {
                ldm_x4(ah[mi], swaddr64(base,        wm * 64 + 16 * mi + lrow, 2 * ks + lsel));
                ldm_x4(al[mi], swaddr64(base + 8192, wm * 64 + 16 * mi + lrow, 2 * ks + lsel));
            }
#pragma unroll
            for (int p = 0; p < 2; p++) {
                ldm_x4(bh[p], swaddr64(base + 16384, wn * 32 + 16 * p + lrow, 2 * ks + lsel));
                ldm_x4(bl[p], swaddr64(base + 24576, wn * 32 + 16 * p + lrow, 2 * ks + lsel));
            }
#pragma unroll
            for (int mi = 0; mi < 4; mi++)
#pragma unroll
                for (int nt = 0; nt < 4; nt++) {
                    int p = nt >> 1, q = nt & 1;
                    mma_bf16(acc[mi][nt], ah[mi], bh[p][q], bh[p][q + 2]);
                    mma_bf16(acc[mi][nt], ah[mi], bl[p][q], bl[p][q + 2]);
                    mma_bf16(acc[mi][nt], al[mi], bh[p][q], bh[p][q + 2]);
                }
        }
    }

    // Epilogue
    const int g = lane >> 2, t4 = lane & 3;
    __nv_bfloat16 *dhi = nullptr, *dlo = nullptr;
    if (mode == 0) {
        int w = blockIdx.z;
        dhi = (w == 0) ? g_qhi : (w == 1) ? g_khi : g_vhi;
        dlo = (w == 0) ? g_qlo : (w == 1) ? g_klo : g_vlo;
    }
#pragma unroll
    for (int mi = 0; mi < 4; mi++)
#pragma unroll
        for (int nt = 0; nt < 4; nt++)
#pragma unroll
            for (int hf = 0; hf < 2; hf++) {
                int row = m0 + wm * 64 + 16 * mi + g + 8 * hf;
                int col = n0 + wn * 32 + 8 * nt + 2 * t4;
                float v0 = acc[mi][nt][2 * hf];
                float v1 = acc[mi][nt][2 * hf + 1];
                if (mode == 0) {
                    int bb = row >> 11, s = row & (Sv - 1);
                    int hh = col >> 6, hd = col & 63;
                    size_t di = ((size_t)(bb * Hv + hh) * Sv + s) * HDv + hd;
                    uint32_t lo2;
                    uint32_t hi2 = split2(v0, v1, lo2);
                    *(uint32_t*)(dhi + di) = hi2;
                    *(uint32_t*)(dlo + di) = lo2;
                } else {
                    out[(size_t)row * Dv + col]     = v0 + bias[col];
                    out[(size_t)row * Dv + col + 1] = v1 + bias[col + 1];
                }
            }
}

// ---------------------------------------------------------------------------
// Tensor-core causal flash attention. BM=128, BN=64, 8 warps (warp = 16 rows).
// Q + double-buffered K/V via cp.async. 3-pass bf16 hi/lo for QK^T and PV.
// Writes ctx as bf16 hi/lo [B*S, D].
// smem: Qhi 0..16K, Qlo 16K..32K, KV stage0 32K..64K, stage1 64K..96K
//       (each stage: Khi, Klo, Vhi, Vlo at +0, +8K, +16K, +24K)
// ---------------------------------------------------------------------------
#define ATT_SMEM (96 * 1024)

__global__ __launch_bounds__(256, 2) void attn_tc()
{
    extern __shared__ char sm_[];
    uint32_t sb = smem_to_u32(sm_);
    const int tid = threadIdx.x, wid = tid >> 5, lane = tid & 31;
    const int qt = blockIdx.x, h = blockIdx.y, b = blockIdx.z;
    const int q0 = qt * 128;
    const size_t hb = (size_t)(b * Hv + h) * Sv * HDv;
    const __nv_bfloat16 *Qhi = g_qhi + hb, *Qlo = g_qlo + hb;
    const __nv_bfloat16 *Khi = g_khi + hb, *Klo = g_klo + hb;
    const __nv_bfloat16 *Vhi = g_vhi + hb, *Vlo = g_vlo + hb;

    // Q tiles via cp.async (128 rows x 8 units, hi+lo)
#pragma unroll
    for (int it = 0; it < 4; it++) {
        int idx = tid + it * 256;        // 0..1023
        int row = idx >> 3, u = idx & 7;
        size_t gs = (size_t)(q0 + row) * HDv + u * 8;
        cp16(swaddr(sb,         row, u), Qhi + gs);
        cp16(swaddr(sb + 16384, row, u), Qlo + gs);
    }
    CP_COMMIT();

    auto issue_kv = [&](int kt, int stg) {
        uint32_t base = sb + 32768 + (uint32_t)stg * 32768;
        int k0r = kt * 64;
#pragma unroll
        for (int it = 0; it < 2; it++) {
            int idx = tid + it * 256;    // 0..511 (64 rows x 8 units)
            int row = idx >> 3, u = idx & 7;
            size_t gs = (size_t)(k0r + row) * HDv + u * 8;
            cp16(swaddr(base,         row, u), Khi + gs);
            cp16(swaddr(base + 8192,  row, u), Klo + gs);
            cp16(swaddr(base + 16384, row, u), Vhi + gs);
            cp16(swaddr(base + 24576, row, u), Vlo + gs);
        }
        CP_COMMIT();
    };

    issue_kv(0, 0);

    const int lrow = lane & 15, lsel = lane >> 4, g = lane >> 2, t4 = lane & 3;
    const float scl = 0.125f;

    float mreg[2] = {-1e30f, -1e30f}, lreg[2] = {0.f, 0.f};
    float o[8][4];
#pragma unroll
    for (int nt = 0; nt < 8; nt++)
#pragma unroll
        for (int k = 0; k < 4; k++) o[nt][k] = 0.f;

    const int gq0 = q0 + wid * 16 + g;
    const int gq1 = gq0 + 8;
    const int ntiles = 2 * qt + 2;

    for (int kt = 0; kt < ntiles; kt++) {
        CP_WAIT(0);
        __syncthreads();
        if (kt + 1 < ntiles) issue_kv(kt + 1, (kt + 1) & 1);

        uint32_t kvb = sb + 32768 + (uint32_t)(kt & 1) * 32768;
        const int k0r = kt * 64;

        // ---- S = Q K^T (3-pass hi/lo) ----
        float s[8][4];
#pragma unroll
        for (int nt = 0; nt < 8; nt++)
#pragma unroll
            for (int k = 0; k < 4; k++) s[nt][k] = 0.f;

#pragma unroll
        for (int ks = 0; ks < 4; ks++) {
            uint32_t qh[4], ql[4];
            ldm_x4(qh, swaddr(sb,         wid * 16 + lrow, 2 * ks + lsel));
            ldm_x4(ql, swaddr(sb + 16384, wid * 16 + lrow, 2 * ks + lsel));
            uint32_t kh[4][4], kl[4][4];
#pragma unroll
            for (int p = 0; p < 4; p++) {
                ldm_x4(kh[p], swaddr(kvb,        16 * p + lrow, 2 * ks + lsel));
                ldm_x4(kl[p], swaddr(kvb + 8192, 16 * p + lrow, 2 * ks + lsel));
            }
#pragma unroll
            for (int nt = 0; nt < 8; nt++) {
                int p = nt >> 1, q = nt & 1;
                mma_bf16(s[nt], qh, kh[p][q], kh[p][q + 2]);
                mma_bf16(s[nt], qh, kl[p][q], kl[p][q + 2]);
                mma_bf16(s[nt], ql, kh[p][q], kh[p][q + 2]);
            }
        }

        // scale + causal mask (only diagonal-region tiles can mask)
        const bool diag = (kt >= 2 * qt);
#pragma unroll
        for (int nt = 0; nt < 8; nt++) {
            int c0 = k0r + 8 * nt + 2 * t4;
            s[nt][0] *= scl; s[nt][1] *= scl; s[nt][2] *= scl; s[nt][3] *= scl;
            if (diag) {
                if (c0 > gq0)     s[nt][0] = -1e30f;
                if (c0 + 1 > gq0) s[nt][1] = -1e30f;
                if (c0 > gq1)     s[nt][2] = -1e30f;
                if (c0 + 1 > gq1) s[nt][3] = -1e30f;
            }
        }

        // ---- online softmax ----
        float rm0 = -1e30f, rm1 = -1e30f;
#pragma unroll
        for (int nt = 0; nt < 8; nt++) {
            rm0 = fmaxf(rm0, fmaxf(s[nt][0], s[nt][1]));
            rm1 = fmaxf(rm1, fmaxf(s[nt][2], s[nt][3]));
        }
        rm0 = fmaxf(rm0, __shfl_xor_sync(0xffffffffu, rm0, 1));
        rm0 = fmaxf(rm0, __shfl_xor_sync(0xffffffffu, rm0, 2));
        rm1 = fmaxf(rm1, __shfl_xor_sync(0xffffffffu, rm1, 1));
        rm1 = fmaxf(rm1, __shfl_xor_sync(0xffffffffu, rm1, 2));

        float nm0 = fmaxf(mreg[0], rm0), nm1 = fmaxf(mreg[1], rm1);
        float a0 = __expf(mreg[0] - nm0), a1 = __expf(mreg[1] - nm1);
        mreg[0] = nm0; mreg[1] = nm1;

        float rs0 = 0.f, rs1 = 0.f;
#pragma unroll
        for (int nt = 0; nt < 8; nt++) {
            s[nt][0] = __expf(s[nt][0] - nm0);
            s[nt][1] = __expf(s[nt][1] - nm0);
            s[nt][2] = __expf(s[nt][2] - nm1);
            s[nt][3] = __expf(s[nt][3] - nm1);
            rs0 += s[nt][0] + s[nt][1];
            rs1 += s[nt][2] + s[nt][3];
        }
        rs0 += __shfl_xor_sync(0xffffffffu, rs0, 1);
        rs0 += __shfl_xor_sync(0xffffffffu, rs0, 2);
        rs1 += __shfl_xor_sync(0xffffffffu, rs1, 1);
        rs1 += __shfl_xor_sync(0xffffffffu, rs1, 2);
        lreg[0] = lreg[0] * a0 + rs0;
        lreg[1] = lreg[1] * a1 + rs1;

#pragma unroll
        for (int nt = 0; nt < 8; nt++) {
            o[nt][0] *= a0; o[nt][1] *= a0;
            o[nt][2] *= a1; o[nt][3] *= a1;
        }

        // ---- O += P V (3-pass) ----
#pragma unroll
        for (int ks = 0; ks < 4; ks++) {
            uint32_t ph[4], pl[4];
            ph[0] = split2(s[2 * ks][0],     s[2 * ks][1],     pl[0]);
            ph[1] = split2(s[2 * ks][2],     s[2 * ks][3],     pl[1]);
            ph[2] = split2(s[2 * ks + 1][0], s[2 * ks + 1][1], pl[2]);
            ph[3] = split2(s[2 * ks + 1][2], s[2 * ks + 1][3], pl[3]);

            uint32_t vh[4][4], vl[4][4];
#pragma unroll
            for (int p2 = 0; p2 < 4; p2++) {
                ldm_x4_t(vh[p2], swaddr(kvb + 16384, 16 * ks + lrow, 2 * p2 + lsel));
                ldm_x4_t(vl[p2], swaddr(kvb + 24576, 16 * ks + lrow, 2 * p2 + lsel));
            }
#pragma unroll
            for (int nt = 0; nt < 8; nt++) {
                int p2 = nt >> 1, q = nt & 1;
                uint32_t b0h = vh[p2][2 * q], b1h = vh[p2][2 * q + 1];
                uint32_t b0l = vl[p2][2 * q], b1l = vl[p2][2 * q + 1];
                mma_bf16(o[nt], ph, b0h, b1h);
                mma_bf16(o[nt], pl, b0h, b1h);
                mma_bf16(o[nt], ph, b0l, b1l);
            }
        }
    }

    // Epilogue: normalize, split hi/lo, write ctx [B*S, D]
    float inv0 = 1.f / lreg[0], inv1 = 1.f / lreg[1];
#pragma unroll
    for (int nt = 0; nt < 8; nt++) {
        int col = h * HDv + 8 * nt + 2 * t4;
        size_t r0 = ((size_t)b * Sv + gq0) * Dv + col;
        size_t r1 = ((size_t)b * Sv + gq1) * Dv + col;
        uint32_t lo2;
        uint32_t hi2 = split2(o[nt][0] * inv0, o[nt][1] * inv0, lo2);
        *(uint32_t*)(g_chi + r0) = hi2;
        *(uint32_t*)(g_clo + r0) = lo2;
        hi2 = split2(o[nt][2] * inv1, o[nt][3] * inv1, lo2);
        *(uint32_t*)(g_chi + r1) = hi2;
        *(uint32_t*)(g_clo + r1) = lo2;
    }
}

// ---------------------------------------------------------------------------
extern "C" void kernel_launch(void* const* d_in, const int* in_sizes, int n_in,
                              void* d_out, int out_size)
{
    const float* X  = (const float*)d_in[0];
    const float* Wq = (const float*)d_in[1];
    const float* Wk = (const float*)d_in[2];
    const float* Wv = (const float*)d_in[3];
    const float* Wo = (const float*)d_in[4];
    const float* bo = (const float*)d_in[5];
    float* out = (float*)d_out;

    cudaFuncSetAttribute(gemm_tc,
                         cudaFuncAttributeMaxDynamicSharedMemorySize, GEMM_SMEM);
    cudaFuncSetAttribute(attn_tc,
                         cudaFuncAttributeMaxDynamicSharedMemorySize, ATT_SMEM);

    const int nX4 = Mv * Dv / 4;
    const int nW4 = Dv * Dv / 4;

    // 1. bf16 hi/lo splits
    cvt_x_kernel<<<nX4 / 256, 256>>>((const float4*)X);
    cvt_w_kernel<<<dim3(nW4 / 256, 4), 256>>>(
        (const float4*)Wq, (const float4*)Wk, (const float4*)Wv, (const float4*)Wo);

    // 2. Q/K/V projections (tensor cores)
    gemm_tc<<<dim3(Dv / 128, Mv / 128, 3), 256, GEMM_SMEM>>>(0, nullptr, nullptr);

    // 3. Causal flash attention (tensor cores)
    attn_tc<<<dim3(Sv / 128, Hv, Bv), 256, ATT_SMEM>>>();

    // 4. Output projection + bias (tensor cores)
    gemm_tc<<<dim3(Dv / 128, Mv / 128, 1), 256, GEMM_SMEM>>>(1, out, bo);
}

// round 7
// speedup vs baseline: 4.9384x; 1.0177x over previous
#include <cuda_runtime.h>
#include <cuda_bf16.h>
#include <math.h>
#include <stdint.h>

// Problem constants
#define Bv 4
#define Sv 2048
#define Dv 1024
#define Hv 16
#define HDv 64
#define Mv (Bv * Sv)   // 8192 rows

// ---------------------------------------------------------------------------
// PTX helpers (sm_80+ baseline: mma.sync / ldmatrix / cp.async)
// ---------------------------------------------------------------------------
__device__ __forceinline__ uint32_t smem_to_u32(const void* p) {
    uint32_t a;
    asm("{ .reg .u64 t; cvta.to.shared.u64 t, %1; cvt.u32.u64 %0, t; }"
        : "=r"(a) : "l"(p));
    return a;
}

__device__ __forceinline__ void mma_bf16(float* c, const uint32_t* a,
                                         uint32_t b0, uint32_t b1) {
    asm volatile(
        "mma.sync.aligned.m16n8k16.row.col.f32.bf16.bf16.f32 "
        "{%0,%1,%2,%3}, {%4,%5,%6,%7}, {%8,%9}, {%0,%1,%2,%3};\n"
        : "+f"(c[0]), "+f"(c[1]), "+f"(c[2]), "+f"(c[3])
        : "r"(a[0]), "r"(a[1]), "r"(a[2]), "r"(a[3]), "r"(b0), "r"(b1));
}

__device__ __forceinline__ void ldm_x4(uint32_t* r, uint32_t a) {
    asm volatile("ldmatrix.sync.aligned.m8n8.x4.shared.b16 {%0,%1,%2,%3}, [%4];"
        : "=r"(r[0]), "=r"(r[1]), "=r"(r[2]), "=r"(r[3]) : "r"(a));
}
__device__ __forceinline__ void ldm_x4_t(uint32_t* r, uint32_t a) {
    asm volatile("ldmatrix.sync.aligned.m8n8.x4.trans.shared.b16 {%0,%1,%2,%3}, [%4];"
        : "=r"(r[0]), "=r"(r[1]), "=r"(r[2]), "=r"(r[3]) : "r"(a));
}

__device__ __forceinline__ void cp16(uint32_t dst, const void* src) {
    asm volatile("cp.async.cg.shared.global [%0], [%1], 16;"
        :: "r"(dst), "l"(src) : "memory");
}
#define CP_COMMIT() asm volatile("cp.async.commit_group;" ::: "memory")
#define CP_WAIT(N)  asm volatile("cp.async.wait_group %0;" :: "n"(N) : "memory")

// swizzled byte offsets (computed once; k-steps advance via XOR, see below)
__device__ __forceinline__ uint32_t swoff128(int row, int unit) {
    uint32_t off = (uint32_t)row * 128u + (uint32_t)unit * 16u;
    return off ^ ((off >> 3) & 0x70u);
}
__device__ __forceinline__ uint32_t swoff64(int row, int unit) {
    uint32_t off = (uint32_t)row * 64u + (uint32_t)unit * 16u;
    return off ^ ((off >> 3) & 0x30u);
}

// split float pair -> packed bf16x2 hi (returned) and lo (out param)
__device__ __forceinline__ uint32_t split2(float x, float y, uint32_t& lo) {
    __nv_bfloat16 hx = __float2bfloat16(x);
    __nv_bfloat16 hy = __float2bfloat16(y);
    __nv_bfloat162 hp(hx, hy);
    __nv_bfloat162 lp(__float2bfloat16(x - __bfloat162float(hx)),
                      __float2bfloat16(y - __bfloat162float(hy)));
    lo = *(uint32_t*)&lp;
    return *(uint32_t*)&hp;
}

// ---------------------------------------------------------------------------
// Scratch (allocation-guard-safe: __device__ globals), all bf16 hi/lo pairs
// ---------------------------------------------------------------------------
#define QKV_ELEMS ((size_t)Bv * Hv * Sv * HDv)
__device__ __nv_bfloat16 g_qhi[QKV_ELEMS], g_qlo[QKV_ELEMS];
__device__ __nv_bfloat16 g_khi[QKV_ELEMS], g_klo[QKV_ELEMS];
__device__ __nv_bfloat16 g_vhi[QKV_ELEMS], g_vlo[QKV_ELEMS];
__device__ __nv_bfloat16 g_xhi[(size_t)Mv * Dv], g_xlo[(size_t)Mv * Dv];
__device__ __nv_bfloat16 g_whi[(size_t)4 * Dv * Dv], g_wlo[(size_t)4 * Dv * Dv];
__device__ __nv_bfloat16 g_chi[(size_t)Mv * Dv], g_clo[(size_t)Mv * Dv];

// ---------------------------------------------------------------------------
// fp32 -> bf16 hi/lo splits
// ---------------------------------------------------------------------------
__global__ __launch_bounds__(256) void cvt_x_kernel(const float4* __restrict__ src)
{
    int i = blockIdx.x * blockDim.x + threadIdx.x;
    float4 v = src[i];
    uint32_t l0, l1;
    uint32_t h0 = split2(v.x, v.y, l0);
    uint32_t h1 = split2(v.z, v.w, l1);
    uint32_t* hp = (uint32_t*)(g_xhi + (size_t)i * 4);
    uint32_t* lp = (uint32_t*)(g_xlo + (size_t)i * 4);
    hp[0] = h0; hp[1] = h1;
    lp[0] = l0; lp[1] = l1;
}

__global__ __launch_bounds__(256) void cvt_w_kernel(
    const float4* __restrict__ w0, const float4* __restrict__ w1,
    const float4* __restrict__ w2, const float4* __restrict__ w3)
{
    int i = blockIdx.x * blockDim.x + threadIdx.x;
    int w = blockIdx.y;
    const float4* src = (w == 0) ? w0 : (w == 1) ? w1 : (w == 2) ? w2 : w3;
    __nv_bfloat16* hi = g_whi + (size_t)w * Dv * Dv;
    __nv_bfloat16* lo = g_wlo + (size_t)w * Dv * Dv;
    float4 v = src[i];
    uint32_t l0, l1;
    uint32_t h0 = split2(v.x, v.y, l0);
    uint32_t h1 = split2(v.z, v.w, l1);
    uint32_t* hp = (uint32_t*)(hi + (size_t)i * 4);
    uint32_t* lp = (uint32_t*)(lo + (size_t)i * 4);
    hp[0] = h0; hp[1] = h1;
    lp[0] = l0; lp[1] = l1;
}

// ---------------------------------------------------------------------------
// Tensor-core GEMM: Out[M,N] = A[M,K] @ B[N,K]^T, bf16 hi/lo 3-pass, fp32 acc.
// Block 128x128, BK=32, 8 warps (warp tile 64x32), 3-stage cp.async pipeline.
// ---------------------------------------------------------------------------
#define STG 32768
#define GEMM_SMEM (3 * STG)
#define NCH 32

__global__ __launch_bounds__(256, 2) void gemm_tc(
    int mode, float* __restrict__ out, const float* __restrict__ bias)
{
    extern __shared__ char smem[];
    uint32_t sb = smem_to_u32(smem);
    const int tid = threadIdx.x;
    const int wid = tid >> 5, lane = tid & 31;
    const int wm = wid & 1, wn = wid >> 1;
    const int m0 = blockIdx.y * 128, n0 = blockIdx.x * 128;

    const __nv_bfloat16 *Ahi, *Alo, *Bhi, *Blo;
    if (mode == 0) {
        int w = blockIdx.z;
        Ahi = g_xhi; Alo = g_xlo;
        Bhi = g_whi + (size_t)w * Dv * Dv;
        Blo = g_wlo + (size_t)w * Dv * Dv;
    } else {
        Ahi = g_chi; Alo = g_clo;
        Bhi = g_whi + (size_t)3 * Dv * Dv;
        Blo = g_wlo + (size_t)3 * Dv * Dv;
    }

    // Precomputed cp.async store offsets + gmem source offsets (per thread)
    const int r0_ = tid >> 2, u0_ = tid & 3;
    const int r1_ = (tid + 256) >> 2;
    const uint32_t st0 = swoff64(r0_, u0_), st1 = swoff64(r1_, u0_);
    const size_t ga0 = (size_t)(m0 + r0_) * Dv + u0_ * 8;
    const size_t ga1 = (size_t)(m0 + r1_) * Dv + u0_ * 8;
    const size_t gb0 = (size_t)(n0 + r0_) * Dv + u0_ * 8;
    const size_t gb1 = (size_t)(n0 + r1_) * Dv + u0_ * 8;

    auto issue = [&](int ch, int stg) {
        uint32_t base = sb + (uint32_t)stg * STG;
        int k0 = ch * 32;
        cp16(base + st0,          Ahi + ga0 + k0);
        cp16(base + 8192 + st0,   Alo + ga0 + k0);
        cp16(base + 16384 + st0,  Bhi + gb0 + k0);
        cp16(base + 24576 + st0,  Blo + gb0 + k0);
        cp16(base + st1,          Ahi + ga1 + k0);
        cp16(base + 8192 + st1,   Alo + ga1 + k0);
        cp16(base + 16384 + st1,  Bhi + gb1 + k0);
        cp16(base + 24576 + st1,  Blo + gb1 + k0);
        CP_COMMIT();
    };

    float acc[4][4][4];
#pragma unroll
    for (int i = 0; i < 4; i++)
#pragma unroll
        for (int j = 0; j < 4; j++)
#pragma unroll
            for (int k = 0; k < 4; k++) acc[i][j][k] = 0.f;

    issue(0, 0);
    issue(1, 1);

    const int lrow = lane & 15, lsel = lane >> 4;

    // Precomputed ldmatrix offsets at unit=lsel (bit5/6 of offset clear).
    // k-step advance: swizzled(off + ks*32) == swizzled(off) ^ (ks*32)
    // (stride touches only bits 5-6; swizzle mask reads row bits >= 7).
    uint32_t a_off[4], b_off[2];
#pragma unroll
    for (int mi = 0; mi < 4; mi++)
        a_off[mi] = swoff64(wm * 64 + 16 * mi + lrow, lsel);
#pragma unroll
    for (int p = 0; p < 2; p++)
        b_off[p] = swoff64(wn * 32 + 16 * p + lrow, lsel);

    for (int ch = 0; ch < NCH; ch++) {
        if (ch < NCH - 1) { CP_WAIT(1); } else { CP_WAIT(0); }
        __syncthreads();
        if (ch + 2 < NCH) issue(ch + 2, (ch + 2) % 3);

        uint32_t base = sb + (uint32_t)(ch % 3) * STG;
#pragma unroll
        for (int ks = 0; ks < 2; ks++) {
            const uint32_t kso = (uint32_t)ks * 32u;
            uint32_t ah[4][4], al[4][4], bh[2][4], bl[2][4];
#pragma unroll
            for (int mi = 0; mi < 4; mi++) {
                ldm_x4(ah[mi], base + (a_off[mi] ^ kso));
                ldm_x4(al[mi], base + 8192 + (a_off[mi] ^ kso));
            }
#pragma unroll
            for (int p = 0; p < 2; p++) {
                ldm_x4(bh[p], base + 16384 + (b_off[p] ^ kso));
                ldm_x4(bl[p], base + 24576 + (b_off[p] ^ kso));
            }
#pragma unroll
            for (int mi = 0; mi < 4; mi++)
#pragma unroll
                for (int nt = 0; nt < 4; nt++) {
                    int p = nt >> 1, q = nt & 1;
                    mma_bf16(acc[mi][nt], ah[mi], bh[p][q], bh[p][q + 2]);
                    mma_bf16(acc[mi][nt], ah[mi], bl[p][q], bl[p][q + 2]);
                    mma_bf16(acc[mi][nt], al[mi], bh[p][q], bh[p][q + 2]);
                }
        }
    }

    // Epilogue
    const int g = lane >> 2, t4 = lane & 3;
    __nv_bfloat16 *dhi = nullptr, *dlo = nullptr;
    float oscl = 1.0f;
    if (mode == 0) {
        int w = blockIdx.z;
        dhi = (w == 0) ? g_qhi : (w == 1) ? g_khi : g_vhi;
        dlo = (w == 0) ? g_qlo : (w == 1) ? g_klo : g_vlo;
        if (w == 0) oscl = 0.125f;   // pre-scale Q by 1/sqrt(HD) (exact pow2)
    }
#pragma unroll
    for (int mi = 0; mi < 4; mi++)
#pragma unroll
        for (int nt = 0; nt < 4; nt++)
#pragma unroll
            for (int hf = 0; hf < 2; hf++) {
                int row = m0 + wm * 64 + 16 * mi + g + 8 * hf;
                int col = n0 + wn * 32 + 8 * nt + 2 * t4;
                float v0 = acc[mi][nt][2 * hf];
                float v1 = acc[mi][nt][2 * hf + 1];
                if (mode == 0) {
                    v0 *= oscl; v1 *= oscl;
                    int bb = row >> 11, s = row & (Sv - 1);
                    int hh = col >> 6, hd = col & 63;
                    size_t di = ((size_t)(bb * Hv + hh) * Sv + s) * HDv + hd;
                    uint32_t lo2;
                    uint32_t hi2 = split2(v0, v1, lo2);
                    *(uint32_t*)(dhi + di) = hi2;
                    *(uint32_t*)(dlo + di) = lo2;
                } else {
                    out[(size_t)row * Dv + col]     = v0 + bias[col];
                    out[(size_t)row * Dv + col + 1] = v1 + bias[col + 1];
                }
            }
}

// ---------------------------------------------------------------------------
// Tensor-core causal flash attention. BM=128, BN=64, 8 warps.
// Q pre-scaled by 1/8. Descending-qt CTA order for tail packing.
// ---------------------------------------------------------------------------
#define ATT_SMEM (96 * 1024)

__global__ __launch_bounds__(256, 2) void attn_tc()
{
    extern __shared__ char sm_[];
    uint32_t sb = smem_to_u32(sm_);
    const int tid = threadIdx.x, wid = tid >> 5, lane = tid & 31;
    const int qt = gridDim.x - 1 - blockIdx.x;   // big tiles first
    const int h = blockIdx.y, b = blockIdx.z;
    const int q0 = qt * 128;
    const size_t hb = (size_t)(b * Hv + h) * Sv * HDv;
    const __nv_bfloat16 *Qhi = g_qhi + hb, *Qlo = g_qlo + hb;
    const __nv_bfloat16 *Khi = g_khi + hb, *Klo = g_klo + hb;
    const __nv_bfloat16 *Vhi = g_vhi + hb, *Vlo = g_vlo + hb;

    // Q tiles via cp.async (128 rows x 8 units, hi+lo)
#pragma unroll
    for (int it = 0; it < 4; it++) {
        int idx = tid + it * 256;
        int row = idx >> 3, u = idx & 7;
        uint32_t so = swoff128(row, u);
        size_t gs = (size_t)(q0 + row) * HDv + u * 8;
        cp16(sb + so,         Qhi + gs);
        cp16(sb + 16384 + so, Qlo + gs);
    }
    CP_COMMIT();

    // Precomputed KV store offsets + source offsets
    const int kr0 = tid >> 3, ku0 = tid & 7;
    const int kr1 = (tid + 256) >> 3;
    const uint32_t kst0 = swoff128(kr0, ku0), kst1 = swoff128(kr1, ku0);
    const size_t ksrc0 = (size_t)kr0 * HDv + ku0 * 8;
    const size_t ksrc1 = (size_t)kr1 * HDv + ku0 * 8;

    auto issue_kv = [&](int kt, int stg) {
        uint32_t base = sb + 32768 + (uint32_t)stg * 32768;
        size_t adv = (size_t)kt * 64 * HDv;
        cp16(base + kst0,          Khi + adv + ksrc0);
        cp16(base + 8192 + kst0,   Klo + adv + ksrc0);
        cp16(base + 16384 + kst0,  Vhi + adv + ksrc0);
        cp16(base + 24576 + kst0,  Vlo + adv + ksrc0);
        cp16(base + kst1,          Khi + adv + ksrc1);
        cp16(base + 8192 + kst1,   Klo + adv + ksrc1);
        cp16(base + 16384 + kst1,  Vhi + adv + ksrc1);
        cp16(base + 24576 + kst1,  Vlo + adv + ksrc1);
        CP_COMMIT();
    };

    issue_kv(0, 0);

    const int lrow = lane & 15, lsel = lane >> 4, g = lane >> 2, t4 = lane & 3;

    // Precomputed ldmatrix offsets at unit=lsel (offset bits 5-6 clear).
    // k-step: swizzled ^ (ks*32). V row-advance (+16 rows): +2048 bytes,
    // which is above all swizzle-affected bits -> plain add is exact.
    const uint32_t q_off = swoff128(wid * 16 + lrow, lsel);
    uint32_t k_off[4], v_off[4];
#pragma unroll
    for (int p = 0; p < 4; p++) k_off[p] = swoff128(16 * p + lrow, lsel);
#pragma unroll
    for (int p2 = 0; p2 < 4; p2++) v_off[p2] = swoff128(lrow, 2 * p2 + lsel);

    float mreg[2] = {-1e30f, -1e30f}, lreg[2] = {0.f, 0.f};
    float o[8][4];
#pragma unroll
    for (int nt = 0; nt < 8; nt++)
#pragma unroll
        for (int k = 0; k < 4; k++) o[nt][k] = 0.f;

    const int gq0 = q0 + wid * 16 + g;
    const int gq1 = gq0 + 8;
    const int ntiles = 2 * qt + 2;

    for (int kt = 0; kt < ntiles; kt++) {
        CP_WAIT(0);
        __syncthreads();
        if (kt + 1 < ntiles) issue_kv(kt + 1, (kt + 1) & 1);

        uint32_t kvb = sb + 32768 + (uint32_t)(kt & 1) * 32768;
        const int k0r = kt * 64;

        // ---- S = Q K^T (3-pass hi/lo); Q pre-scaled ----
        float s[8][4];
#pragma unroll
        for (int nt = 0; nt < 8; nt++)
#pragma unroll
            for (int k = 0; k < 4; k++) s[nt][k] = 0.f;

#pragma unroll
        for (int ks = 0; ks < 4; ks++) {
            const uint32_t kso = (uint32_t)ks * 32u;
            uint32_t qh[4], ql[4];
            ldm_x4(qh, sb + (q_off ^ kso));
            ldm_x4(ql, sb + 16384 + (q_off ^ kso));
            uint32_t kh[4][4], kl[4][4];
#pragma unroll
            for (int p = 0; p < 4; p++) {
                ldm_x4(kh[p], kvb + (k_off[p] ^ kso));
                ldm_x4(kl[p], kvb + 8192 + (k_off[p] ^ kso));
            }
#pragma unroll
            for (int nt = 0; nt < 8; nt++) {
                int p = nt >> 1, q = nt & 1;
                mma_bf16(s[nt], qh, kh[p][q], kh[p][q + 2]);
                mma_bf16(s[nt], qh, kl[p][q], kl[p][q + 2]);
                mma_bf16(s[nt], ql, kh[p][q], kh[p][q + 2]);
            }
        }

        // causal mask (only diagonal-region tiles)
        if (kt >= 2 * qt) {
#pragma unroll
            for (int nt = 0; nt < 8; nt++) {
                int c0 = k0r + 8 * nt + 2 * t4;
                if (c0 > gq0)     s[nt][0] = -1e30f;
                if (c0 + 1 > gq0) s[nt][1] = -1e30f;
                if (c0 > gq1)     s[nt][2] = -1e30f;
                if (c0 + 1 > gq1) s[nt][3] = -1e30f;
            }
        }

        // ---- online softmax ----
        float rm0 = -1e30f, rm1 = -1e30f;
#pragma unroll
        for (int nt = 0; nt < 8; nt++) {
            rm0 = fmaxf(rm0, fmaxf(s[nt][0], s[nt][1]));
            rm1 = fmaxf(rm1, fmaxf(s[nt][2], s[nt][3]));
        }
        rm0 = fmaxf(rm0, __shfl_xor_sync(0xffffffffu, rm0, 1));
        rm0 = fmaxf(rm0, __shfl_xor_sync(0xffffffffu, rm0, 2));
        rm1 = fmaxf(rm1, __shfl_xor_sync(0xffffffffu, rm1, 1));
        rm1 = fmaxf(rm1, __shfl_xor_sync(0xffffffffu, rm1, 2));

        float nm0 = fmaxf(mreg[0], rm0), nm1 = fmaxf(mreg[1], rm1);
        float a0 = __expf(mreg[0] - nm0), a1 = __expf(mreg[1] - nm1);
        mreg[0] = nm0; mreg[1] = nm1;

        float rs0 = 0.f, rs1 = 0.f;
#pragma unroll
        for (int nt = 0; nt < 8; nt++) {
            s[nt][0] = __expf(s[nt][0] - nm0);
            s[nt][1] = __expf(s[nt][1] - nm0);
            s[nt][2] = __expf(s[nt][2] - nm1);
            s[nt][3] = __expf(s[nt][3] - nm1);
            rs0 += s[nt][0] + s[nt][1];
            rs1 += s[nt][2] + s[nt][3];
        }
        rs0 += __shfl_xor_sync(0xffffffffu, rs0, 1);
        rs0 += __shfl_xor_sync(0xffffffffu, rs0, 2);
        rs1 += __shfl_xor_sync(0xffffffffu, rs1, 1);
        rs1 += __shfl_xor_sync(0xffffffffu, rs1, 2);
        lreg[0] = lreg[0] * a0 + rs0;
        lreg[1] = lreg[1] * a1 + rs1;

#pragma unroll
        for (int nt = 0; nt < 8; nt++) {
            o[nt][0] *= a0; o[nt][1] *= a0;
            o[nt][2] *= a1; o[nt][3] *= a1;
        }

        // ---- O += P V (3-pass) ----
#pragma unroll
        for (int ks = 0; ks < 4; ks++) {
            const uint32_t vko = (uint32_t)ks * 2048u;
            uint32_t ph[4], pl[4];
            ph[0] = split2(s[2 * ks][0],     s[2 * ks][1],     pl[0]);
            ph[1] = split2(s[2 * ks][2],     s[2 * ks][3],     pl[1]);
            ph[2] = split2(s[2 * ks + 1][0], s[2 * ks + 1][1], pl[2]);
            ph[3] = split2(s[2 * ks + 1][2], s[2 * ks + 1][3], pl[3]);

            uint32_t vh[4][4], vl[4][4];
#pragma unroll
            for (int p2 = 0; p2 < 4; p2++) {
                ldm_x4_t(vh[p2], kvb + 16384 + v_off[p2] + vko);
                ldm_x4_t(vl[p2], kvb + 24576 + v_off[p2] + vko);
            }
#pragma unroll
            for (int nt = 0; nt < 8; nt++) {
                int p2 = nt >> 1, q = nt & 1;
                uint32_t b0h = vh[p2][2 * q], b1h = vh[p2][2 * q + 1];
                uint32_t b0l = vl[p2][2 * q], b1l = vl[p2][2 * q + 1];
                mma_bf16(o[nt], ph, b0h, b1h);
                mma_bf16(o[nt], pl, b0h, b1h);
                mma_bf16(o[nt], ph, b0l, b1l);
            }
        }
    }

    // Epilogue: normalize, split hi/lo, write ctx [B*S, D]
    float inv0 = 1.f / lreg[0], inv1 = 1.f / lreg[1];
#pragma unroll
    for (int nt = 0; nt < 8; nt++) {
        int col = h * HDv + 8 * nt + 2 * t4;
        size_t r0 = ((size_t)b * Sv + gq0) * Dv + col;
        size_t r1 = ((size_t)b * Sv + gq1) * Dv + col;
        uint32_t lo2;
        uint32_t hi2 = split2(o[nt][0] * inv0, o[nt][1] * inv0, lo2);
        *(uint32_t*)(g_chi + r0) = hi2;
        *(uint32_t*)(g_clo + r0) = lo2;
        hi2 = split2(o[nt][2] * inv1, o[nt][3] * inv1, lo2);
        *(uint32_t*)(g_chi + r1) = hi2;
        *(uint32_t*)(g_clo + r1) = lo2;
    }
}

// ---------------------------------------------------------------------------
extern "C" void kernel_launch(void* const* d_in, const int* in_sizes, int n_in,
                              void* d_out, int out_size)
{
    const float* X  = (const float*)d_in[0];
    const float* Wq = (const float*)d_in[1];
    const float* Wk = (const float*)d_in[2];
    const float* Wv = (const float*)d_in[3];
    const float* Wo = (const float*)d_in[4];
    const float* bo = (const float*)d_in[5];
    float* out = (float*)d_out;

    cudaFuncSetAttribute(gemm_tc,
                         cudaFuncAttributeMaxDynamicSharedMemorySize, GEMM_SMEM);
    cudaFuncSetAttribute(attn_tc,
                         cudaFuncAttributeMaxDynamicSharedMemorySize, ATT_SMEM);

    const int nX4 = Mv * Dv / 4;
    const int nW4 = Dv * Dv / 4;

    cvt_x_kernel<<<nX4 / 256, 256>>>((const float4*)X);
    cvt_w_kernel<<<dim3(nW4 / 256, 4), 256>>>(
        (const float4*)Wq, (const float4*)Wk, (const float4*)Wv, (const float4*)Wo);

    gemm_tc<<<dim3(Dv / 128, Mv / 128, 3), 256, GEMM_SMEM>>>(0, nullptr, nullptr);

    attn_tc<<<dim3(Sv / 128, Hv, Bv), 256, ATT_SMEM>>>();

    gemm_tc<<<dim3(Dv / 128, Mv / 128, 1), 256, GEMM_SMEM>>>(1, out, bo);
}